// round 15
// baseline (speedup 1.0000x reference)
#include <cuda_runtime.h>
#include <math.h>

#define BB 16
#define CIN 256
#define CO 128
#define HH 32
#define WW 32
#define HO 64
#define WO 64
#define NOFF 27

typedef unsigned long long u64;

// ---------------- f32x2 helpers (sm_103a packed fp32 FMA) ----------------
__device__ __forceinline__ u64 pack2(float x, float y) {
    u64 r; asm("mov.b64 %0,{%1,%2};" : "=l"(r) : "f"(x), "f"(y)); return r;
}
__device__ __forceinline__ void fma2(u64& d, u64 a, u64 b) {
    asm("fma.rn.f32x2 %0,%1,%2,%0;" : "+l"(d) : "l"(a), "l"(b));
}
__device__ __forceinline__ float2 unpack2(u64 v) {
    float2 f; asm("mov.b64 {%0,%1},%2;" : "=f"(f.x), "=f"(f.y) : "l"(v)); return f;
}

// ---------------- scratch (static device globals; no allocation) ----------------
__device__ float g_off [BB * NOFF * HH * WW];  // offset-conv partial (c 0..127, +bias)
__device__ float g_offb[BB * NOFF * HH * WW];  // offset-conv partial (c 128..255)
__device__ float g_y0 [BB * CO * HH * WW];     // deform-conv partial (c 0..127)
__device__ float g_y0b[BB * CO * HH * WW];     // deform-conv partial (c 128..255)
__device__ float g_y1[BB * CO * HO * WO];      // transposed-conv output (pre-BN)
__device__ float g_sc1[CO], g_sh1[CO];         // BN1 folded scale/shift
__device__ float g_sc2[CO], g_sh2[CO];         // BN2 folded scale/shift
__device__ float2 g_wTp[64 * 36 * 64];         // w_dcn pairs [chunk][tap36][o]: (w[o],w[o+64])
__device__ float g_wT2[16 * 128 * 128];        // w_up re-layout [tap16][i][o]
__device__ float g_xT[BB * HH * WW * CIN];     // x channel-last [b][p][c]

// =================================================================================
// Weight / layout prep kernels
// =================================================================================
__global__ void k_wprepP(const float* __restrict__ w_dcn) {
    int idx = blockIdx.x * 256 + threadIdx.x;          // 64*36*64 = 147456
    int o = idx & 63;
    int t = (idx >> 6) % 36;
    int chunk = idx / 2304;
    int c = chunk * 4 + t / 9;
    int k = t % 9;
    g_wTp[idx] = make_float2(w_dcn[(o * CIN + c) * 9 + k],
                             w_dcn[((o + 64) * CIN + c) * 9 + k]);
}
__global__ void k_wprep2(const float* __restrict__ w_up) {
    int idx = blockIdx.x * 256 + threadIdx.x;          // 16*128*128
    int o = idx & 127;
    int i = (idx >> 7) & 127;
    int tap = idx >> 14;
    g_wT2[idx] = w_up[(i * CO + o) * 16 + tap];
}
// x[b][c][p] -> g_xT[b][p][c], tiled transpose (coalesced both sides)
__global__ void k_xT(const float* __restrict__ x) {
    __shared__ float t[32][33];
    const int b  = blockIdx.z;
    const int c0 = blockIdx.y * 32;
    const int p0 = blockIdx.x * 32;
    const int tx = threadIdx.x, ty = threadIdx.y;      // (32,8)
#pragma unroll
    for (int n = 0; n < 4; n++)
        t[ty + n * 8][tx] = x[(((size_t)b * CIN + c0 + ty + n * 8) << 10) + p0 + tx];
    __syncthreads();
#pragma unroll
    for (int n = 0; n < 4; n++)
        g_xT[(((size_t)b << 10) + p0 + ty + n * 8) * CIN + c0 + tx] = t[tx][ty + n * 8];
}

// =================================================================================
// Kernel 1: offset conv 3x3 (R10/R12 version — measured best). 2 rows x half-C.
// =================================================================================
__global__ void __launch_bounds__(256) k_offset(const float* __restrict__ x,
                                                const float* __restrict__ w_off,
                                                const float* __restrict__ b_off) {
    const int i0 = blockIdx.x * 2;
    const int b  = blockIdx.y;
    const int z  = blockIdx.z;         // C half
    const int tx = threadIdx.x;        // oc lane (27 active)
    const int ty = threadIdx.y;
    const int tid = ty * 32 + tx;
    const int row = ty >> 2;           // 0..1
    const int pxq = ty & 3;            // 8-px group

    __shared__ __align__(16) float xs[16][4][36];
    __shared__ float ws[16][9][32];

    u64 acc[4];
#pragma unroll
    for (int q = 0; q < 4; q++) acc[q] = 0ull;

    const int cbase = z * 128;
    for (int c0 = cbase; c0 < cbase + 128; c0 += 16) {
        for (int s = tid; s < 2304; s += 256) {
            int c = s / 144, r = (s % 144) / 36, col = s % 36;
            int ii = i0 + r - 1, jj = col - 1;
            float v = 0.f;
            if (col < 34 && ii >= 0 && ii < HH && jj >= 0 && jj < WW)
                v = x[((b * CIN + c0 + c) * HH + ii) * WW + jj];
            xs[c][r][col] = v;
        }
        for (int s = tid; s < 3888; s += 256) {
            int oc = s / 144, c = (s % 144) / 9, tap = s % 9;
            ws[c][tap][oc] = w_off[(oc * CIN + c0 + c) * 9 + tap];
        }
        __syncthreads();

#pragma unroll 2
        for (int c = 0; c < 16; c++) {
            u64 wd[9];
#pragma unroll
            for (int k = 0; k < 9; k++) { float w = ws[c][k][tx]; wd[k] = pack2(w, w); }
#pragma unroll
            for (int kh = 0; kh < 3; kh++) {
                const float* xr = &xs[c][row + kh][pxq * 8];
                float4 A  = *(const float4*)xr;
                float4 Bv = *(const float4*)(xr + 4);
                float2 Cv = *(const float2*)(xr + 8);
                float xv[10];
                xv[0] = A.x;  xv[1] = A.y;  xv[2] = A.z;  xv[3] = A.w;
                xv[4] = Bv.x; xv[5] = Bv.y; xv[6] = Bv.z; xv[7] = Bv.w;
                xv[8] = Cv.x; xv[9] = Cv.y;
#pragma unroll
                for (int s = 0; s < 4; s++) {
                    u64 Pa = pack2(xv[2 * s],     xv[2 * s + 1]);
                    u64 Pb = pack2(xv[2 * s + 1], xv[2 * s + 2]);
                    u64 Pc = pack2(xv[2 * s + 2], xv[2 * s + 3]);
                    fma2(acc[s], Pa, wd[kh * 3 + 0]);
                    fma2(acc[s], Pb, wd[kh * 3 + 1]);
                    fma2(acc[s], Pc, wd[kh * 3 + 2]);
                }
            }
        }
        __syncthreads();
    }
    if (tx < NOFF) {
        float bo = (z == 0) ? b_off[tx] : 0.f;
        float2 e0 = unpack2(acc[0]), e1 = unpack2(acc[1]);
        float2 e2 = unpack2(acc[2]), e3 = unpack2(acc[3]);
        float* base = z ? g_offb : g_off;
        float* dst = &base[((b * NOFF + tx) * HH + (i0 + row)) * WW + pxq * 8];
        *(float4*)dst       = make_float4(e0.x + bo, e0.y + bo, e1.x + bo, e1.y + bo);
        *(float4*)(dst + 4) = make_float4(e2.x + bo, e2.y + bo, e3.x + bo, e3.y + bo);
    }
}

// =================================================================================
// Kernel 2: deformable conv v6 (unchanged from R12 — measured good).
// =================================================================================
__global__ void __launch_bounds__(256, 2) k_deform() {
    const int b  = blockIdx.y;
    const int i0 = blockIdx.x * 4;              // 4 rows = 128 px
    const int zz = blockIdx.z;                  // C half
    const int tid = threadIdx.x;

    __shared__ float sm[18432];                 // 73.7 KB
    int4*   idxs  = (int4*)sm;
    float4* wgts  = (float4*)(sm + 4608);
    float*  sampA = sm + 9216;
    float*  sampB = sm + 13824;

    for (int s = tid; s < 1152; s += 256) {
        int k = s >> 7, p = s & 127;
        int i = i0 + (p >> 5), j = p & 31;
        int o0 = ((b * NOFF + 2 * k) * HH + i) * WW + j;
        int o1 = ((b * NOFF + 2 * k + 1) * HH + i) * WW + j;
        int o2 = ((b * NOFF + 18 + k) * HH + i) * WW + j;
        float dy = g_off[o0] + g_offb[o0];
        float dx = g_off[o1] + g_offb[o1];
        float mv = g_off[o2] + g_offb[o2];
        float msk = 1.f / (1.f + expf(-mv));
        float py = (float)(i + (k / 3) - 1) + dy;
        float px = (float)(j + (k % 3) - 1) + dx;
        float fy = floorf(py), fx = floorf(px);
        float wy = py - fy, wx = px - fx;

        int4 id; float4 wv;
        {
            bool v = (fy >= 0.f) && (fy <= 31.f) && (fx >= 0.f) && (fx <= 31.f);
            int yi = min(max((int)fy, 0), 31), xi = min(max((int)fx, 0), 31);
            id.x = (yi * WW + xi) * CIN; wv.x = (1.f - wy) * (1.f - wx) * (v ? msk : 0.f);
        }
        {
            float xc = fx + 1.f;
            bool v = (fy >= 0.f) && (fy <= 31.f) && (xc >= 0.f) && (xc <= 31.f);
            int yi = min(max((int)fy, 0), 31), xi = min(max((int)xc, 0), 31);
            id.y = (yi * WW + xi) * CIN; wv.y = (1.f - wy) * wx * (v ? msk : 0.f);
        }
        {
            float yc = fy + 1.f;
            bool v = (yc >= 0.f) && (yc <= 31.f) && (fx >= 0.f) && (fx <= 31.f);
            int yi = min(max((int)yc, 0), 31), xi = min(max((int)fx, 0), 31);
            id.z = (yi * WW + xi) * CIN; wv.z = wy * (1.f - wx) * (v ? msk : 0.f);
        }
        {
            float yc = fy + 1.f, xc = fx + 1.f;
            bool v = (yc >= 0.f) && (yc <= 31.f) && (xc >= 0.f) && (xc <= 31.f);
            int yi = min(max((int)yc, 0), 31), xi = min(max((int)xc, 0), 31);
            id.w = (yi * WW + xi) * CIN; wv.w = wy * wx * (v ? msk : 0.f);
        }
        idxs[s] = id; wgts[s] = wv;
    }
    __syncthreads();

    u64 accA[16], accB[16];
#pragma unroll
    for (int q = 0; q < 16; q++) { accA[q] = 0ull; accB[q] = 0ull; }

    const int oq  = tid & 63;
    const int pxq = tid >> 6;
    const float* xtb = g_xT + (((size_t)b) << 10) * CIN;
    const int chunk0 = zz * 32;

#define GATHER(c0v, sbuf)                                                             \
    for (int s = tid; s < 1152; s += 256) {                                           \
        int4 id = idxs[s]; float4 wv = wgts[s];                                       \
        float4 ca = *(const float4*)&xtb[id.x + (c0v)];                               \
        float4 cb = *(const float4*)&xtb[id.y + (c0v)];                               \
        float4 cc = *(const float4*)&xtb[id.z + (c0v)];                               \
        float4 cd = *(const float4*)&xtb[id.w + (c0v)];                               \
        float* dst = (sbuf) + s;                                                      \
        dst[0]    = fmaf(wv.x, ca.x, fmaf(wv.y, cb.x, fmaf(wv.z, cc.x, wv.w * cd.x))); \
        dst[1152] = fmaf(wv.x, ca.y, fmaf(wv.y, cb.y, fmaf(wv.z, cc.y, wv.w * cd.y))); \
        dst[2304] = fmaf(wv.x, ca.z, fmaf(wv.y, cb.z, fmaf(wv.z, cc.z, wv.w * cd.z))); \
        dst[3456] = fmaf(wv.x, ca.w, fmaf(wv.y, cb.w, fmaf(wv.z, cc.w, wv.w * cd.w))); \
    }

    GATHER(chunk0 * 4, sampA);
    __syncthreads();

    for (int it = 0; it < 32; it++) {
        float* scur = (it & 1) ? sampB : sampA;
        if (it + 1 < 32) {
            float* snxt = (it & 1) ? sampA : sampB;
            GATHER((chunk0 + it + 1) * 4, snxt);
        }
        const float2* wp = g_wTp + (size_t)(chunk0 + it) * 2304 + oq;
#pragma unroll
        for (int cc = 0; cc < 4; cc++) {
#pragma unroll
            for (int k = 0; k < 9; k++) {
                float2 w = wp[(cc * 9 + k) * 64];
                u64 w2a = pack2(w.x, w.x);
                u64 w2b = pack2(w.y, w.y);
                const ulonglong2* sp =
                    (const ulonglong2*)&scur[(cc * 9 + k) * 128 + pxq * 32];
#pragma unroll
                for (int q = 0; q < 8; q++) {
                    ulonglong2 sv = sp[q];
                    fma2(accA[2 * q],     sv.x, w2a);
                    fma2(accA[2 * q + 1], sv.y, w2a);
                    fma2(accB[2 * q],     sv.x, w2b);
                    fma2(accB[2 * q + 1], sv.y, w2b);
                }
            }
        }
        __syncthreads();
    }
#undef GATHER

    float* outs = sm;
#pragma unroll
    for (int q = 0; q < 8; q++) {
        float2 a0 = unpack2(accA[2 * q]);
        float2 a1 = unpack2(accA[2 * q + 1]);
        *(float4*)&outs[oq * 132 + pxq * 32 + q * 4] = make_float4(a0.x, a0.y, a1.x, a1.y);
        float2 b0 = unpack2(accB[2 * q]);
        float2 b1 = unpack2(accB[2 * q + 1]);
        *(float4*)&outs[(oq + 64) * 132 + pxq * 32 + q * 4] = make_float4(b0.x, b0.y, b1.x, b1.y);
    }
    __syncthreads();
    float* dstb = zz ? g_y0b : g_y0;
    for (int r = 0; r < 16; r++) {
        int e = tid + r * 256;
        int oo = e >> 5, p4 = e & 31;
        float4 v = *(const float4*)&outs[oo * 132 + p4 * 4];
        *(float4*)&dstb[(b * CO + oo) * (HH * WW) + i0 * 32 + p4 * 4] = v;
    }
}

// =================================================================================
// Kernel 3/5: BN stats -> folded scale/shift. which=0 sums the two y0 partials.
// =================================================================================
__global__ void k_bnstats(int which, const float* __restrict__ gamma,
                          const float* __restrict__ beta) {
    const int c = blockIdx.x;
    const int plane = which ? (HO * WO) : (HH * WW);
    const int npc = plane * BB;
    const int p4c = plane >> 2;

    float s = 0.f, s2 = 0.f;
    for (int e = threadIdx.x; e < (npc >> 2); e += 256) {
        int bb = e / p4c, p4 = e % p4c;
        size_t off = ((size_t)(bb * CO + c)) * plane + p4 * 4;
        float4 v;
        if (which) {
            v = *(const float4*)&g_y1[off];
        } else {
            float4 a = *(const float4*)&g_y0[off];
            float4 bq = *(const float4*)&g_y0b[off];
            v = make_float4(a.x + bq.x, a.y + bq.y, a.z + bq.z, a.w + bq.w);
        }
        s  += v.x + v.y + v.z + v.w;
        s2 += v.x * v.x + v.y * v.y + v.z * v.z + v.w * v.w;
    }
#pragma unroll
    for (int off = 16; off > 0; off >>= 1) {
        s  += __shfl_down_sync(0xffffffffu, s, off);
        s2 += __shfl_down_sync(0xffffffffu, s2, off);
    }
    __shared__ float red[64];
    int wid = threadIdx.x >> 5, lane = threadIdx.x & 31;
    if (lane == 0) { red[wid] = s; red[wid + 32] = s2; }
    __syncthreads();
    if (threadIdx.x == 0) {
        float S = 0.f, S2 = 0.f;
#pragma unroll
        for (int w = 0; w < 8; w++) { S += red[w]; S2 += red[w + 32]; }
        float inv = 1.f / (float)npc;
        float mu = S * inv;
        float var = S2 * inv - mu * mu;
        float rs = rsqrtf(var + 1e-5f);
        float sc = rs * gamma[c];
        if (which) { g_sc2[c] = sc; g_sh2[c] = beta[c] - mu * sc; }
        else       { g_sc1[c] = sc; g_sh1[c] = beta[c] - mu * sc; }
    }
}

// =================================================================================
// Kernel 4: transposed conv v2 — ROW-PAIRED. Block computes oy_a and oy_b=oy_a+2
// (same parity -> same tap quads). 3 shared input rows serve both outputs; weights
// staged once for 2x output; r1's E/O packs feed both rows. BN1+ReLU fused on read.
// =================================================================================
__global__ void __launch_bounds__(256, 2) k_convt() {
    const int p  = blockIdx.x;                 // 32 row-pairs
    const int b  = blockIdx.y;
    const int oy_a = (p >> 1) * 4 + (p & 1);
    const int oy_b = oy_a + 2;
    const int tid = threadIdx.x;
    const int o   = tid & 127;
    const int oxg = tid >> 7;
    const int xb  = oxg * 16;

    __shared__ float sm[18112];                // yin 2x864 + wsh 2x8192 = 72.4 KB
    float* yinb[2] = { sm, sm + 864 };
    float* wshb[2] = { sm + 1728, sm + 1728 + 8192 };

    const int iy0   = (oy_a + 1) >> 1;         // = row r1
    const int kh0   = oy_a - 2 * iy0 + 1;
    const int kh1   = kh0 + 2;
    const int rbase = iy0 - 1;                 // rows rbase..rbase+2

    u64 accA_e[8], accA_o[8], accB_e[8], accB_o[8];
#pragma unroll
    for (int q = 0; q < 8; q++) {
        accA_e[q] = 0ull; accA_o[q] = 0ull; accB_e[q] = 0ull; accB_o[q] = 0ull;
    }

#define STAGE(i0v, buf)                                                          \
    {                                                                            \
        float* yin = yinb[buf];                                                  \
        float* wsh = wshb[buf];                                                  \
        for (int s = tid; s < 864; s += 256) {                                   \
            int ii = s / 108; int rem = s % 108;                                 \
            int rsl = rem / 36; int col = rem % 36;                              \
            int iy = rbase + rsl;                                                \
            int ix = col - 1;                                                    \
            float v = 0.f;                                                       \
            if (col < 34 && iy >= 0 && iy < HH && ix >= 0 && ix < WW) {          \
                int ic = (i0v) + ii;                                             \
                int gi = ((b * CO + ic) * HH + iy) * WW + ix;                    \
                float raw = g_y0[gi] + g_y0b[gi];                                \
                v = fmaxf(fmaf(raw, g_sc1[ic], g_sh1[ic]), 0.f);                 \
            }                                                                    \
            yin[s] = v;                                                          \
        }                                                                        \
        for (int n = 0; n < 8; n++) {                                            \
            int s4 = tid + n * 256;                                              \
            int t = s4 >> 8;                                                     \
            int rem = s4 & 255;                                                  \
            int tap = (t < 4) ? (kh0 * 4 + t) : (kh1 * 4 + (t - 4));             \
            float4 v = *(const float4*)&g_wT2[(tap << 14) + ((i0v) << 7) + rem * 4]; \
            *(float4*)&wsh[s4 * 4] = v;                                          \
        }                                                                        \
    }

// load 18 yv floats from a yin row and pack even/odd pair registers
#define LOADPACK(yr, E, O)                                                       \
    {                                                                            \
        float yv[18];                                                            \
        float4 t0 = *(const float4*)(yr);                                        \
        float4 t1 = *(const float4*)(yr + 4);                                    \
        float4 t2 = *(const float4*)(yr + 8);                                    \
        float4 t3 = *(const float4*)(yr + 12);                                   \
        yv[0] = t0.x; yv[1] = t0.y; yv[2] = t0.z; yv[3] = t0.w;                  \
        yv[4] = t1.x; yv[5] = t1.y; yv[6] = t1.z; yv[7] = t1.w;                  \
        yv[8] = t2.x; yv[9] = t2.y; yv[10] = t2.z; yv[11] = t2.w;                \
        yv[12] = t3.x; yv[13] = t3.y; yv[14] = t3.z; yv[15] = t3.w;              \
        yv[16] = (yr)[16]; yv[17] = (yr)[17];                                    \
        _Pragma("unroll")                                                        \
        for (int s = 0; s < 9; s++) E[s] = pack2(yv[2 * s], yv[2 * s + 1]);      \
        _Pragma("unroll")                                                        \
        for (int s = 0; s < 8; s++) O[s] = pack2(yv[2 * s + 1], yv[2 * s + 2]);  \
    }

#define APPLY(ae, ao, E, O, W0, W1, W2, W3)                                      \
    _Pragma("unroll")                                                            \
    for (int s = 0; s < 8; s++) {                                                \
        fma2(ae[s], O[s],     W1);                                               \
        fma2(ae[s], E[s],     W3);                                               \
        fma2(ao[s], E[s + 1], W0);                                               \
        fma2(ao[s], O[s],     W2);                                               \
    }

    STAGE(0, 0);

    for (int itn = 0; itn < 16; itn++) {
        __syncthreads();
        if (itn + 1 < 16) STAGE((itn + 1) * 8, (itn + 1) & 1);

        const int buf = itn & 1;
        const float* yin = yinb[buf];
        const float* wsh = wshb[buf];
#pragma unroll
        for (int ii = 0; ii < 8; ii++) {
            float wA0 = wsh[(0 * 8 + ii) * 128 + o];
            float wA1 = wsh[(1 * 8 + ii) * 128 + o];
            float wA2 = wsh[(2 * 8 + ii) * 128 + o];
            float wA3 = wsh[(3 * 8 + ii) * 128 + o];
            float wB0 = wsh[(4 * 8 + ii) * 128 + o];
            float wB1 = wsh[(5 * 8 + ii) * 128 + o];
            float wB2 = wsh[(6 * 8 + ii) * 128 + o];
            float wB3 = wsh[(7 * 8 + ii) * 128 + o];
            u64 wA0d = pack2(wA0, wA0), wA1d = pack2(wA1, wA1);
            u64 wA2d = pack2(wA2, wA2), wA3d = pack2(wA3, wA3);
            u64 wB0d = pack2(wB0, wB0), wB1d = pack2(wB1, wB1);
            u64 wB2d = pack2(wB2, wB2), wB3d = pack2(wB3, wB3);

            u64 E[9], O[8];
            // r0 (iy0-1): out_a with kh1 quad (B)
            LOADPACK(&yin[(ii * 3 + 0) * 36 + xb], E, O);
            APPLY(accA_e, accA_o, E, O, wB0d, wB1d, wB2d, wB3d);
            // r1 (iy0): out_a with kh0 quad (A), out_b with kh1 quad (B) — pack once
            LOADPACK(&yin[(ii * 3 + 1) * 36 + xb], E, O);
            APPLY(accA_e, accA_o, E, O, wA0d, wA1d, wA2d, wA3d);
            APPLY(accB_e, accB_o, E, O, wB0d, wB1d, wB2d, wB3d);
            // r2 (iy0+1): out_b with kh0 quad (A)
            LOADPACK(&yin[(ii * 3 + 2) * 36 + xb], E, O);
            APPLY(accB_e, accB_o, E, O, wA0d, wA1d, wA2d, wA3d);
        }
    }
#undef STAGE
#undef LOADPACK
#undef APPLY

    __syncthreads();
    // epilogue: both rows transposed in SMEM (2 x 128 x 68 = 17408 <= 18112)
    float* outs = sm;
#pragma unroll
    for (int s = 0; s < 8; s++) {
        float2 ea = unpack2(accA_e[s]);
        float2 da = unpack2(accA_o[s]);
        *(float4*)&outs[o * 68 + oxg * 32 + 4 * s] = make_float4(ea.x, da.x, ea.y, da.y);
        float2 eb = unpack2(accB_e[s]);
        float2 db = unpack2(accB_o[s]);
        *(float4*)&outs[8704 + o * 68 + oxg * 32 + 4 * s] = make_float4(eb.x, db.x, eb.y, db.y);
    }
    __syncthreads();
    for (int r = 0; r < 32; r++) {
        int e = tid + r * 256;
        int oo = e >> 6, ox = e & 63;
        size_t base = ((size_t)(b * CO + oo) * HO) * WO + ox;
        g_y1[base + (size_t)oy_a * WO] = outs[oo * 68 + ox];
        g_y1[base + (size_t)oy_b * WO] = outs[8704 + oo * 68 + ox];
    }
}

// =================================================================================
// Kernel 6: final BN2 + ReLU -> d_out
// =================================================================================
__global__ void k_bnapply(float* __restrict__ out) {
    int idx4 = blockIdx.x * 256 + threadIdx.x;
    int c = (idx4 >> 10) & 127;
    float4 v = *(const float4*)&g_y1[(size_t)idx4 * 4];
    float sc = g_sc2[c], sh = g_sh2[c];
    v.x = fmaxf(fmaf(v.x, sc, sh), 0.f);
    v.y = fmaxf(fmaf(v.y, sc, sh), 0.f);
    v.z = fmaxf(fmaf(v.z, sc, sh), 0.f);
    v.w = fmaxf(fmaf(v.w, sc, sh), 0.f);
    *(float4*)&out[(size_t)idx4 * 4] = v;
}

// =================================================================================
extern "C" void kernel_launch(void* const* d_in, const int* in_sizes, int n_in,
                              void* d_out, int out_size) {
    const float* x     = (const float*)d_in[0];
    const float* w_off = (const float*)d_in[1];
    const float* b_off = (const float*)d_in[2];
    const float* w_dcn = (const float*)d_in[3];
    // d_in[4] = b_dcn: cancels exactly through BN1 — unused
    const float* g1    = (const float*)d_in[5];
    const float* bt1   = (const float*)d_in[6];
    const float* w_up  = (const float*)d_in[7];
    const float* g2    = (const float*)d_in[8];
    const float* bt2   = (const float*)d_in[9];
    float* out = (float*)d_out;

    k_wprepP <<<576, 256>>>(w_dcn);
    k_wprep2 <<<1024, 256>>>(w_up);
    k_xT     <<<dim3(32, 8, 16), dim3(32, 8)>>>(x);
    k_offset <<<dim3(HH / 2, BB, 2), dim3(32, 8)>>>(x, w_off, b_off);
    k_deform <<<dim3(HH / 4, BB, 2), 256>>>();
    k_bnstats<<<CO, 256>>>(0, g1, bt1);
    k_convt  <<<dim3(32, BB), 256>>>();
    k_bnstats<<<CO, 256>>>(1, g2, bt2);
    k_bnapply<<<(BB * CO * HO * WO / 4) / 256, 256>>>(out);
}

// round 16
// speedup vs baseline: 1.0724x; 1.0724x over previous
#include <cuda_runtime.h>
#include <math.h>

#define BB 16
#define CIN 256
#define CO 128
#define HH 32
#define WW 32
#define HO 64
#define WO 64
#define NOFF 27

typedef unsigned long long u64;

// ---------------- f32x2 helpers (sm_103a packed fp32 FMA) ----------------
__device__ __forceinline__ u64 pack2(float x, float y) {
    u64 r; asm("mov.b64 %0,{%1,%2};" : "=l"(r) : "f"(x), "f"(y)); return r;
}
__device__ __forceinline__ void fma2(u64& d, u64 a, u64 b) {
    asm("fma.rn.f32x2 %0,%1,%2,%0;" : "+l"(d) : "l"(a), "l"(b));
}
__device__ __forceinline__ float2 unpack2(u64 v) {
    float2 f; asm("mov.b64 {%0,%1},%2;" : "=f"(f.x), "=f"(f.y) : "l"(v)); return f;
}

// ---------------- scratch (static device globals; no allocation) ----------------
__device__ float g_off [BB * NOFF * HH * WW];  // offset-conv partial (c 0..127, +bias)
__device__ float g_offb[BB * NOFF * HH * WW];  // offset-conv partial (c 128..255)
__device__ float g_y0 [BB * CO * HH * WW];     // deform-conv partial (c 0..127)
__device__ float g_y0b[BB * CO * HH * WW];     // deform-conv partial (c 128..255)
__device__ float g_y1[BB * CO * HO * WO];      // transposed-conv output (pre-BN)
__device__ float g_sc1[CO], g_sh1[CO];         // BN1 folded scale/shift
__device__ float g_sc2[CO], g_sh2[CO];         // BN2 folded scale/shift
__device__ float2 g_wTp[64 * 36 * 64];         // w_dcn pairs [chunk][tap36][o]: (w[o],w[o+64])
__device__ float g_wT2[16 * 128 * 128];        // w_up re-layout [tap16][i][o]
__device__ float2 g_wOd[256 * 9 * 32];         // w_off dup pairs [cglob][tap][oc32]: (w,w)
__device__ float g_xT[BB * HH * WW * CIN];     // x channel-last [b][p][c]

// =================================================================================
// Fused prep kernel: wTp (576 blk) | wT2 (1024 blk) | wOd (288 blk) | xT (4096 blk)
// =================================================================================
__global__ void k_prep(const float* __restrict__ w_dcn,
                       const float* __restrict__ w_up,
                       const float* __restrict__ w_off,
                       const float* __restrict__ x) {
    __shared__ float t[32][33];
    const int bid = blockIdx.x;
    const int tid = threadIdx.x;

    if (bid < 576) {                                   // g_wTp: 64*36*64 = 147456
        int idx = bid * 256 + tid;
        int o = idx & 63;
        int tp = (idx >> 6) % 36;
        int chunk = idx / 2304;
        int c = chunk * 4 + tp / 9;
        int k = tp % 9;
        g_wTp[idx] = make_float2(w_dcn[(o * CIN + c) * 9 + k],
                                 w_dcn[((o + 64) * CIN + c) * 9 + k]);
    } else if (bid < 1600) {                           // g_wT2: 16*128*128
        int idx = (bid - 576) * 256 + tid;
        int o = idx & 127;
        int i = (idx >> 7) & 127;
        int tap = idx >> 14;
        g_wT2[idx] = w_up[(i * CO + o) * 16 + tap];
    } else if (bid < 1888) {                           // g_wOd: 256*9*32 = 73728
        int idx = (bid - 1600) * 256 + tid;
        int oc = idx & 31;
        int tap = (idx >> 5) % 9;
        int cg = idx / 288;                            // 0..255
        float v = (oc < NOFF) ? w_off[(oc * CIN + cg) * 9 + tap] : 0.f;
        g_wOd[idx] = make_float2(v, v);
    } else {                                           // xT: 32x8x16 = 4096 blocks
        int r = bid - 1888;
        int b  = r >> 8;
        int c0 = ((r >> 5) & 7) * 32;
        int p0 = (r & 31) * 32;
        int tx = tid & 31, ty = tid >> 5;
#pragma unroll
        for (int n = 0; n < 4; n++)
            t[ty + n * 8][tx] = x[(((size_t)b * CIN + c0 + ty + n * 8) << 10) + p0 + tx];
        __syncthreads();
#pragma unroll
        for (int n = 0; n < 4; n++)
            g_xT[(((size_t)b << 10) + p0 + ty + n * 8) * CIN + c0 + tx] = t[tx][ty + n * 8];
    }
}

// =================================================================================
// Kernel 1: offset conv 3x3 v5. 2 rows x half-C (z-split), grid 512.
// E/O pair factorization (even pairs = aligned LDS.64, only 4 odd packs per
// (c,kh)); weights pre-duplicated as u64 (zero weight packs); flat f4 staging.
// =================================================================================
__global__ void __launch_bounds__(256) k_offset(const float* __restrict__ x,
                                                const float* __restrict__ b_off) {
    const int i0 = blockIdx.x * 2;
    const int b  = blockIdx.y;
    const int z  = blockIdx.z;         // C half
    const int tx = threadIdx.x;        // oc lane (27 active)
    const int ty = threadIdx.y;
    const int tid = ty * 32 + tx;
    const int row = ty >> 2;           // 0..1
    const int pxq = ty & 3;            // 8-px group

    __shared__ __align__(16) float xs[16][4][36];
    __shared__ u64 ws[16][9][32];      // duplicated weight pairs

    u64 acc[4];
#pragma unroll
    for (int q = 0; q < 4; q++) acc[q] = 0ull;

    const int cbase = z * 128;
    for (int c0 = cbase; c0 < cbase + 128; c0 += 16) {
        // stage x: 16c x 4 rows x 36 cols
        for (int s = tid; s < 2304; s += 256) {
            int c = s / 144, r = (s % 144) / 36, col = s % 36;
            int ii = i0 + r - 1, jj = col - 1;
            float v = 0.f;
            if (col < 34 && ii >= 0 && ii < HH && jj >= 0 && jj < WW)
                v = x[((b * CIN + c0 + c) * HH + ii) * WW + jj];
            xs[c][r][col] = v;
        }
        // stage weights: flat float4 copy of 4608 float2 (= 2304 float4)
        {
            const float4* wsrc = (const float4*)(g_wOd + (size_t)(c0 >> 4) * 4608);
            float4* wdst = (float4*)ws;
            for (int s4 = tid; s4 < 2304; s4 += 256) wdst[s4] = wsrc[s4];
        }
        __syncthreads();

#pragma unroll 2
        for (int c = 0; c < 16; c++) {
            u64 wd0 = ws[c][0][tx], wd1 = ws[c][1][tx], wd2 = ws[c][2][tx];
            u64 wd3 = ws[c][3][tx], wd4 = ws[c][4][tx], wd5 = ws[c][5][tx];
            u64 wd6 = ws[c][6][tx], wd7 = ws[c][7][tx], wd8 = ws[c][8][tx];
#pragma unroll
            for (int kh = 0; kh < 3; kh++) {
                u64 w0 = (kh == 0) ? wd0 : (kh == 1) ? wd3 : wd6;
                u64 w1 = (kh == 0) ? wd1 : (kh == 1) ? wd4 : wd7;
                u64 w2 = (kh == 0) ? wd2 : (kh == 1) ? wd5 : wd8;
                const u64* pE = (const u64*)&xs[c][row + kh][pxq * 8];
                u64 E0 = pE[0], E1 = pE[1], E2 = pE[2], E3 = pE[3], E4 = pE[4];
                float2 e0 = unpack2(E0), e1 = unpack2(E1), e2 = unpack2(E2);
                float2 e3 = unpack2(E3), e4 = unpack2(E4);
                u64 O0 = pack2(e0.y, e1.x);
                u64 O1 = pack2(e1.y, e2.x);
                u64 O2 = pack2(e2.y, e3.x);
                u64 O3 = pack2(e3.y, e4.x);
                fma2(acc[0], E0, w0); fma2(acc[0], O0, w1); fma2(acc[0], E1, w2);
                fma2(acc[1], E1, w0); fma2(acc[1], O1, w1); fma2(acc[1], E2, w2);
                fma2(acc[2], E2, w0); fma2(acc[2], O2, w1); fma2(acc[2], E3, w2);
                fma2(acc[3], E3, w0); fma2(acc[3], O3, w1); fma2(acc[3], E4, w2);
            }
        }
        __syncthreads();
    }
    if (tx < NOFF) {
        float bo = (z == 0) ? b_off[tx] : 0.f;
        float2 e0 = unpack2(acc[0]), e1 = unpack2(acc[1]);
        float2 e2 = unpack2(acc[2]), e3 = unpack2(acc[3]);
        float* base = z ? g_offb : g_off;
        float* dst = &base[((b * NOFF + tx) * HH + (i0 + row)) * WW + pxq * 8];
        *(float4*)dst       = make_float4(e0.x + bo, e0.y + bo, e1.x + bo, e1.y + bo);
        *(float4*)(dst + 4) = make_float4(e2.x + bo, e2.y + bo, e3.x + bo, e3.y + bo);
    }
}

// =================================================================================
// Kernel 2: deformable conv v6 (R12 — measured good, untouched).
// =================================================================================
__global__ void __launch_bounds__(256, 2) k_deform() {
    const int b  = blockIdx.y;
    const int i0 = blockIdx.x * 4;              // 4 rows = 128 px
    const int zz = blockIdx.z;                  // C half
    const int tid = threadIdx.x;

    __shared__ float sm[18432];                 // 73.7 KB
    int4*   idxs  = (int4*)sm;
    float4* wgts  = (float4*)(sm + 4608);
    float*  sampA = sm + 9216;
    float*  sampB = sm + 13824;

    for (int s = tid; s < 1152; s += 256) {
        int k = s >> 7, p = s & 127;
        int i = i0 + (p >> 5), j = p & 31;
        int o0 = ((b * NOFF + 2 * k) * HH + i) * WW + j;
        int o1 = ((b * NOFF + 2 * k + 1) * HH + i) * WW + j;
        int o2 = ((b * NOFF + 18 + k) * HH + i) * WW + j;
        float dy = g_off[o0] + g_offb[o0];
        float dx = g_off[o1] + g_offb[o1];
        float mv = g_off[o2] + g_offb[o2];
        float msk = 1.f / (1.f + expf(-mv));
        float py = (float)(i + (k / 3) - 1) + dy;
        float px = (float)(j + (k % 3) - 1) + dx;
        float fy = floorf(py), fx = floorf(px);
        float wy = py - fy, wx = px - fx;

        int4 id; float4 wv;
        {
            bool v = (fy >= 0.f) && (fy <= 31.f) && (fx >= 0.f) && (fx <= 31.f);
            int yi = min(max((int)fy, 0), 31), xi = min(max((int)fx, 0), 31);
            id.x = (yi * WW + xi) * CIN; wv.x = (1.f - wy) * (1.f - wx) * (v ? msk : 0.f);
        }
        {
            float xc = fx + 1.f;
            bool v = (fy >= 0.f) && (fy <= 31.f) && (xc >= 0.f) && (xc <= 31.f);
            int yi = min(max((int)fy, 0), 31), xi = min(max((int)xc, 0), 31);
            id.y = (yi * WW + xi) * CIN; wv.y = (1.f - wy) * wx * (v ? msk : 0.f);
        }
        {
            float yc = fy + 1.f;
            bool v = (yc >= 0.f) && (yc <= 31.f) && (fx >= 0.f) && (fx <= 31.f);
            int yi = min(max((int)yc, 0), 31), xi = min(max((int)fx, 0), 31);
            id.z = (yi * WW + xi) * CIN; wv.z = wy * (1.f - wx) * (v ? msk : 0.f);
        }
        {
            float yc = fy + 1.f, xc = fx + 1.f;
            bool v = (yc >= 0.f) && (yc <= 31.f) && (xc >= 0.f) && (xc <= 31.f);
            int yi = min(max((int)yc, 0), 31), xi = min(max((int)xc, 0), 31);
            id.w = (yi * WW + xi) * CIN; wv.w = wy * wx * (v ? msk : 0.f);
        }
        idxs[s] = id; wgts[s] = wv;
    }
    __syncthreads();

    u64 accA[16], accB[16];
#pragma unroll
    for (int q = 0; q < 16; q++) { accA[q] = 0ull; accB[q] = 0ull; }

    const int oq  = tid & 63;
    const int pxq = tid >> 6;
    const float* xtb = g_xT + (((size_t)b) << 10) * CIN;
    const int chunk0 = zz * 32;

#define GATHER(c0v, sbuf)                                                             \
    for (int s = tid; s < 1152; s += 256) {                                           \
        int4 id = idxs[s]; float4 wv = wgts[s];                                       \
        float4 ca = *(const float4*)&xtb[id.x + (c0v)];                               \
        float4 cb = *(const float4*)&xtb[id.y + (c0v)];                               \
        float4 cc = *(const float4*)&xtb[id.z + (c0v)];                               \
        float4 cd = *(const float4*)&xtb[id.w + (c0v)];                               \
        float* dst = (sbuf) + s;                                                      \
        dst[0]    = fmaf(wv.x, ca.x, fmaf(wv.y, cb.x, fmaf(wv.z, cc.x, wv.w * cd.x))); \
        dst[1152] = fmaf(wv.x, ca.y, fmaf(wv.y, cb.y, fmaf(wv.z, cc.y, wv.w * cd.y))); \
        dst[2304] = fmaf(wv.x, ca.z, fmaf(wv.y, cb.z, fmaf(wv.z, cc.z, wv.w * cd.z))); \
        dst[3456] = fmaf(wv.x, ca.w, fmaf(wv.y, cb.w, fmaf(wv.z, cc.w, wv.w * cd.w))); \
    }

    GATHER(chunk0 * 4, sampA);
    __syncthreads();

    for (int it = 0; it < 32; it++) {
        float* scur = (it & 1) ? sampB : sampA;
        if (it + 1 < 32) {
            float* snxt = (it & 1) ? sampA : sampB;
            GATHER((chunk0 + it + 1) * 4, snxt);
        }
        const float2* wp = g_wTp + (size_t)(chunk0 + it) * 2304 + oq;
#pragma unroll
        for (int cc = 0; cc < 4; cc++) {
#pragma unroll
            for (int k = 0; k < 9; k++) {
                float2 w = wp[(cc * 9 + k) * 64];
                u64 w2a = pack2(w.x, w.x);
                u64 w2b = pack2(w.y, w.y);
                const ulonglong2* sp =
                    (const ulonglong2*)&scur[(cc * 9 + k) * 128 + pxq * 32];
#pragma unroll
                for (int q = 0; q < 8; q++) {
                    ulonglong2 sv = sp[q];
                    fma2(accA[2 * q],     sv.x, w2a);
                    fma2(accA[2 * q + 1], sv.y, w2a);
                    fma2(accB[2 * q],     sv.x, w2b);
                    fma2(accB[2 * q + 1], sv.y, w2b);
                }
            }
        }
        __syncthreads();
    }
#undef GATHER

    float* outs = sm;
#pragma unroll
    for (int q = 0; q < 8; q++) {
        float2 a0 = unpack2(accA[2 * q]);
        float2 a1 = unpack2(accA[2 * q + 1]);
        *(float4*)&outs[oq * 132 + pxq * 32 + q * 4] = make_float4(a0.x, a0.y, a1.x, a1.y);
        float2 b0 = unpack2(accB[2 * q]);
        float2 b1 = unpack2(accB[2 * q + 1]);
        *(float4*)&outs[(oq + 64) * 132 + pxq * 32 + q * 4] = make_float4(b0.x, b0.y, b1.x, b1.y);
    }
    __syncthreads();
    float* dstb = zz ? g_y0b : g_y0;
    for (int r = 0; r < 16; r++) {
        int e = tid + r * 256;
        int oo = e >> 5, p4 = e & 31;
        float4 v = *(const float4*)&outs[oo * 132 + p4 * 4];
        *(float4*)&dstb[(b * CO + oo) * (HH * WW) + i0 * 32 + p4 * 4] = v;
    }
}

// =================================================================================
// Kernel 3/5: BN stats -> folded scale/shift. which=0 sums the two y0 partials.
// =================================================================================
__global__ void k_bnstats(int which, const float* __restrict__ gamma,
                          const float* __restrict__ beta) {
    const int c = blockIdx.x;
    const int plane = which ? (HO * WO) : (HH * WW);
    const int npc = plane * BB;
    const int p4c = plane >> 2;

    float s = 0.f, s2 = 0.f;
    for (int e = threadIdx.x; e < (npc >> 2); e += 256) {
        int bb = e / p4c, p4 = e % p4c;
        size_t off = ((size_t)(bb * CO + c)) * plane + p4 * 4;
        float4 v;
        if (which) {
            v = *(const float4*)&g_y1[off];
        } else {
            float4 a = *(const float4*)&g_y0[off];
            float4 bq = *(const float4*)&g_y0b[off];
            v = make_float4(a.x + bq.x, a.y + bq.y, a.z + bq.z, a.w + bq.w);
        }
        s  += v.x + v.y + v.z + v.w;
        s2 += v.x * v.x + v.y * v.y + v.z * v.z + v.w * v.w;
    }
#pragma unroll
    for (int off = 16; off > 0; off >>= 1) {
        s  += __shfl_down_sync(0xffffffffu, s, off);
        s2 += __shfl_down_sync(0xffffffffu, s2, off);
    }
    __shared__ float red[64];
    int wid = threadIdx.x >> 5, lane = threadIdx.x & 31;
    if (lane == 0) { red[wid] = s; red[wid + 32] = s2; }
    __syncthreads();
    if (threadIdx.x == 0) {
        float S = 0.f, S2 = 0.f;
#pragma unroll
        for (int w = 0; w < 8; w++) { S += red[w]; S2 += red[w + 32]; }
        float inv = 1.f / (float)npc;
        float mu = S * inv;
        float var = S2 * inv - mu * mu;
        float rs = rsqrtf(var + 1e-5f);
        float sc = rs * gamma[c];
        if (which) { g_sc2[c] = sc; g_sh2[c] = beta[c] - mu * sc; }
        else       { g_sc1[c] = sc; g_sh1[c] = beta[c] - mu * sc; }
    }
}

// =================================================================================
// Kernel 4: transposed conv 4x4 s2 p1 (R12 — measured best, untouched).
// =================================================================================
__global__ void __launch_bounds__(256, 3) k_convt() {
    const int oy = blockIdx.x;
    const int b  = blockIdx.y;
    const int tid = threadIdx.x;
    const int o   = tid & 127;
    const int oxg = tid >> 7;
    const int xb  = oxg * 16;

    __shared__ float sm[17536];
    float* yinb[2] = { sm, sm + 576 };
    float* wshb[2] = { sm + 1152, sm + 1152 + 8192 };

    const int iy0 = (oy + 1) >> 1;
    const int kh0 = oy - 2 * iy0 + 1;
    const int iy1 = iy0 - 1;
    const int kh1 = kh0 + 2;
    const bool v0 = (iy0 < HH);
    const bool v1 = (iy1 >= 0);

    u64 acc_e[8], acc_o[8];
#pragma unroll
    for (int q = 0; q < 8; q++) { acc_e[q] = 0ull; acc_o[q] = 0ull; }

#define STAGE(i0v, buf)                                                          \
    {                                                                            \
        float* yin = yinb[buf];                                                  \
        float* wsh = wshb[buf];                                                  \
        for (int s = tid; s < 576; s += 256) {                                   \
            int ii = s / 72; int rem = s % 72;                                   \
            int slot = rem / 36; int col = rem % 36;                             \
            int ix = col - 1;                                                    \
            int iy = slot == 0 ? iy0 : iy1;                                      \
            float v = 0.f;                                                       \
            if (col < 34 && (slot == 0 ? v0 : v1) && ix >= 0 && ix < WW) {       \
                int ic = (i0v) + ii;                                             \
                int gi = ((b * CO + ic) * HH + iy) * WW + ix;                    \
                float raw = g_y0[gi] + g_y0b[gi];                                \
                v = fmaxf(fmaf(raw, g_sc1[ic], g_sh1[ic]), 0.f);                 \
            }                                                                    \
            yin[s] = v;                                                          \
        }                                                                        \
        for (int n = 0; n < 8; n++) {                                            \
            int s4 = tid + n * 256;                                              \
            int t = s4 >> 8;                                                     \
            int rem = s4 & 255;                                                  \
            int tap = (t < 4) ? (kh0 * 4 + t) : (kh1 * 4 + (t - 4));             \
            float4 v = *(const float4*)&g_wT2[(tap << 14) + ((i0v) << 7) + rem * 4]; \
            *(float4*)&wsh[s4 * 4] = v;                                          \
        }                                                                        \
    }

    STAGE(0, 0);

    for (int itn = 0; itn < 16; itn++) {
        __syncthreads();
        if (itn + 1 < 16) STAGE((itn + 1) * 8, (itn + 1) & 1);

        const int buf = itn & 1;
        const float* yin = yinb[buf];
        const float* wsh = wshb[buf];
#pragma unroll
        for (int ii = 0; ii < 8; ii++) {
#pragma unroll
            for (int r = 0; r < 2; r++) {
                float w0 = wsh[((r * 4 + 0) * 8 + ii) * 128 + o];
                float w1 = wsh[((r * 4 + 1) * 8 + ii) * 128 + o];
                float w2 = wsh[((r * 4 + 2) * 8 + ii) * 128 + o];
                float w3 = wsh[((r * 4 + 3) * 8 + ii) * 128 + o];
                u64 w0d = pack2(w0, w0);
                u64 w1d = pack2(w1, w1);
                u64 w2d = pack2(w2, w2);
                u64 w3d = pack2(w3, w3);
                const float* yr = &yin[(ii * 2 + r) * 36 + xb];
                float yv[18];
                float4 t0 = *(const float4*)(yr);
                float4 t1 = *(const float4*)(yr + 4);
                float4 t2 = *(const float4*)(yr + 8);
                float4 t3 = *(const float4*)(yr + 12);
                yv[0] = t0.x; yv[1] = t0.y; yv[2] = t0.z; yv[3] = t0.w;
                yv[4] = t1.x; yv[5] = t1.y; yv[6] = t1.z; yv[7] = t1.w;
                yv[8] = t2.x; yv[9] = t2.y; yv[10] = t2.z; yv[11] = t2.w;
                yv[12] = t3.x; yv[13] = t3.y; yv[14] = t3.z; yv[15] = t3.w;
                yv[16] = yr[16]; yv[17] = yr[17];
                u64 E[9], O[8];
#pragma unroll
                for (int s = 0; s < 9; s++) E[s] = pack2(yv[2 * s], yv[2 * s + 1]);
#pragma unroll
                for (int s = 0; s < 8; s++) O[s] = pack2(yv[2 * s + 1], yv[2 * s + 2]);
#pragma unroll
                for (int s = 0; s < 8; s++) {
                    fma2(acc_e[s], O[s],     w1d);
                    fma2(acc_e[s], E[s],     w3d);
                    fma2(acc_o[s], E[s + 1], w0d);
                    fma2(acc_o[s], O[s],     w2d);
                }
            }
        }
    }
#undef STAGE

    __syncthreads();
    float* outs = sm;
#pragma unroll
    for (int s = 0; s < 8; s++) {
        float2 e = unpack2(acc_e[s]);
        float2 d = unpack2(acc_o[s]);
        *(float4*)&outs[o * 68 + oxg * 32 + 4 * s] = make_float4(e.x, d.x, e.y, d.y);
    }
    __syncthreads();
    for (int r = 0; r < 32; r++) {
        int e = tid + r * 256;
        int oo = e >> 6, ox = e & 63;
        g_y1[((size_t)(b * CO + oo) * HO + oy) * WO + ox] = outs[oo * 68 + ox];
    }
}

// =================================================================================
// Kernel 6: final BN2 + ReLU -> d_out
// =================================================================================
__global__ void k_bnapply(float* __restrict__ out) {
    int idx4 = blockIdx.x * 256 + threadIdx.x;
    int c = (idx4 >> 10) & 127;
    float4 v = *(const float4*)&g_y1[(size_t)idx4 * 4];
    float sc = g_sc2[c], sh = g_sh2[c];
    v.x = fmaxf(fmaf(v.x, sc, sh), 0.f);
    v.y = fmaxf(fmaf(v.y, sc, sh), 0.f);
    v.z = fmaxf(fmaf(v.z, sc, sh), 0.f);
    v.w = fmaxf(fmaf(v.w, sc, sh), 0.f);
    *(float4*)&out[(size_t)idx4 * 4] = v;
}

// =================================================================================
extern "C" void kernel_launch(void* const* d_in, const int* in_sizes, int n_in,
                              void* d_out, int out_size) {
    const float* x     = (const float*)d_in[0];
    const float* w_off = (const float*)d_in[1];
    const float* b_off = (const float*)d_in[2];
    const float* w_dcn = (const float*)d_in[3];
    // d_in[4] = b_dcn: cancels exactly through BN1 — unused
    const float* g1    = (const float*)d_in[5];
    const float* bt1   = (const float*)d_in[6];
    const float* w_up  = (const float*)d_in[7];
    const float* g2    = (const float*)d_in[8];
    const float* bt2   = (const float*)d_in[9];
    float* out = (float*)d_out;

    k_prep   <<<5984, 256>>>(w_dcn, w_up, w_off, x);
    k_offset <<<dim3(HH / 2, BB, 2), dim3(32, 8)>>>(x, b_off);
    k_deform <<<dim3(HH / 4, BB, 2), 256>>>();
    k_bnstats<<<CO, 256>>>(0, g1, bt1);
    k_convt  <<<dim3(HO, BB), 256>>>();
    k_bnstats<<<CO, 256>>>(1, g2, bt2);
    k_bnapply<<<(BB * CO * HO * WO / 4) / 256, 256>>>(out);
}